// round 4
// baseline (speedup 1.0000x reference)
#include <cuda_runtime.h>
#include <cuda_bf16.h>
#include <math.h>
#include <stdint.h>

// ---------------- problem constants ----------------
#define B_SZ   64
#define T_SZ   512
#define D_IN   968
#define HID    128
#define G3     384
#define MROWS  (B_SZ * T_SZ)      // 32768
#define KPAD   1024
#define KCAT   (3 * KPAD)         // 3072: x=[hi|lo|hi] vs w=[hi|hi|lo]
#define NTOT   768

// ---------------- scratch ----------------
__device__ float g_xp[2u * MROWS * G3];
__device__ __nv_bfloat16 g_abf[(size_t)MROWS * KCAT];
__device__ __nv_bfloat16 g_wbf[(size_t)NTOT * KCAT];

// ---------------- helpers ----------------
__device__ __forceinline__ uint32_t smem_u32(const void* p) {
    uint32_t a;
    asm("{ .reg .u64 t; cvta.to.shared.u64 t, %1; cvt.u32.u64 %0, t; }" : "=r"(a) : "l"(p));
    return a;
}
__device__ __forceinline__ void cp16(uint32_t dst, const void* src) {
    asm volatile("cp.async.cg.shared.global [%0], [%1], 16;" :: "r"(dst), "l"(src));
}
__device__ __forceinline__ void cp_commit() {
    asm volatile("cp.async.commit_group;" ::: "memory");
}
__device__ __forceinline__ void cp_wait2() {
    asm volatile("cp.async.wait_group 2;" ::: "memory");
}
__device__ __forceinline__ void ldmx4(uint32_t* r, uint32_t a) {
    asm volatile("ldmatrix.sync.aligned.m8n8.x4.shared.b16 {%0,%1,%2,%3}, [%4];"
                 : "=r"(r[0]), "=r"(r[1]), "=r"(r[2]), "=r"(r[3]) : "r"(a));
}
__device__ __forceinline__ void mma_bf16(float* c, const uint32_t* a, const uint32_t* b) {
    asm volatile("mma.sync.aligned.m16n8k16.row.col.f32.bf16.bf16.f32 "
                 "{%0,%1,%2,%3}, {%4,%5,%6,%7}, {%8,%9}, {%0,%1,%2,%3};"
                 : "+f"(c[0]), "+f"(c[1]), "+f"(c[2]), "+f"(c[3])
                 : "r"(a[0]), "r"(a[1]), "r"(a[2]), "r"(a[3]), "r"(b[0]), "r"(b[1]));
}
__device__ __forceinline__ unsigned long long fma2(unsigned long long a,
                                                   unsigned long long b,
                                                   unsigned long long c) {
    unsigned long long d;
    asm("fma.rn.f32x2 %0, %1, %2, %3;" : "=l"(d) : "l"(a), "l"(b), "l"(c));
    return d;
}
__device__ __forceinline__ unsigned long long add2(unsigned long long a,
                                                   unsigned long long b) {
    unsigned long long d;
    asm("add.rn.f32x2 %0, %1, %2;" : "=l"(d) : "l"(a), "l"(b));
    return d;
}

// =================================================================
// Kernel 0a/0b: fp32 -> split-bf16 (K padded to 1024, 3-term concat)
// =================================================================
__global__ __launch_bounds__(256) void conv_x(const float* __restrict__ x) {
    const int m = blockIdx.x;
    const float* src = x + (size_t)m * D_IN;
    __nv_bfloat16* dst = g_abf + (size_t)m * KCAT;
    for (int k = threadIdx.x; k < KPAD; k += 256) {
        float v = (k < D_IN) ? src[k] : 0.f;
        __nv_bfloat16 hi = __float2bfloat16(v);
        __nv_bfloat16 lo = __float2bfloat16(v - __bfloat162float(hi));
        dst[k]            = hi;
        dst[KPAD + k]     = lo;
        dst[2 * KPAD + k] = hi;
    }
}
__global__ __launch_bounds__(256) void conv_w(const float* __restrict__ w_f,
                                              const float* __restrict__ w_b) {
    const int n = blockIdx.x;
    const float* src = (n < G3) ? (w_f + (size_t)n * D_IN) : (w_b + (size_t)(n - G3) * D_IN);
    __nv_bfloat16* dst = g_wbf + (size_t)n * KCAT;
    for (int k = threadIdx.x; k < KPAD; k += 256) {
        float v = (k < D_IN) ? src[k] : 0.f;
        __nv_bfloat16 hi = __float2bfloat16(v);
        __nv_bfloat16 lo = __float2bfloat16(v - __bfloat162float(hi));
        dst[k]            = hi;
        dst[KPAD + k]     = hi;
        dst[2 * KPAD + k] = lo;
    }
}

// =================================================================
// Kernel 1: HMMA bf16 GEMM.  M=32768, N=768, K=3072.
//   CTA 128x256x32, 8 warps (warp tile 64x64), 3-stage cp.async pipe.
//   80B-padded rows -> conflict-free ldmatrix without swizzle.
// =================================================================
#define BK      32
#define ROWB    80
#define A_BYTES (128 * ROWB)          // 10240
#define B_BYTES (256 * ROWB)          // 20480
#define STAGEB  (A_BYTES + B_BYTES)   // 30720
#define NSTG    (KCAT / BK)           // 96
#define GEMM_SMEM (3 * STAGEB)        // 92160

__global__ __launch_bounds__(256, 1) void gemm_mma(const float* __restrict__ bias_f,
                                                   const float* __restrict__ bias_b) {
    extern __shared__ char smem[];
    const uint32_t sb = smem_u32(smem);
    const int tid  = threadIdx.x;
    const int wid  = tid >> 5;
    const int lane = tid & 31;
    const int wrow = wid >> 2;        // 0..1 (64 rows each)
    const int wcol = wid & 3;         // 0..3 (64 cols each)

    const int m0 = blockIdx.y * 128;
    const int n0 = blockIdx.x * 256;

    const __nv_bfloat16* Ag = g_abf + (size_t)m0 * KCAT;
    const __nv_bfloat16* Bg = g_wbf + (size_t)n0 * KCAT;

    // A loader: 512 chunks, 2/thread.  B loader: 1024 chunks, 4/thread.
    const int alrow = tid >> 1;
    const int alseg = (tid & 1) * 2;

    float acc[4][8][4];
#pragma unroll
    for (int i = 0; i < 4; i++)
#pragma unroll
        for (int j = 0; j < 8; j++)
#pragma unroll
            for (int q = 0; q < 4; q++) acc[i][j][q] = 0.f;

    auto issue = [&](int s) {
        const uint32_t st = sb + (s % 3) * STAGEB;
        const size_t gk = (size_t)s * BK;
        const __nv_bfloat16* arow = Ag + (size_t)alrow * KCAT + gk;
        cp16(st + alrow * ROWB + alseg * 16,       arow + alseg * 8);
        cp16(st + alrow * ROWB + (alseg + 1) * 16, arow + (alseg + 1) * 8);
        const __nv_bfloat16* brow = Bg + (size_t)tid * KCAT + gk;
        const uint32_t bst = st + A_BYTES + tid * ROWB;
#pragma unroll
        for (int c = 0; c < 4; c++) cp16(bst + c * 16, brow + c * 8);
    };

    issue(0); cp_commit();
    issue(1); cp_commit();

    const int a_r = (lane & 15);
    const int a_c = (lane >> 4) * 16;
    const int b_r = (lane & 7) + ((lane >> 4) << 3);
    const int b_c = ((lane >> 3) & 1) * 16;

    for (int s = 0; s < NSTG; s++) {
        __syncthreads();
        if (s + 2 < NSTG) issue(s + 2);
        cp_commit();
        cp_wait2();
        __syncthreads();

        const uint32_t st = sb + (s % 3) * STAGEB;
        const uint32_t aw = st + (wrow * 64 + a_r) * ROWB + a_c;
        const uint32_t bw = st + A_BYTES + (wcol * 64 + b_r) * ROWB + b_c;

#pragma unroll
        for (int kh = 0; kh < 2; kh++) {
            uint32_t afr[4][4], bfr[4][4];
#pragma unroll
            for (int mf = 0; mf < 4; mf++)
                ldmx4(afr[mf], aw + mf * 16 * ROWB + kh * 32);
#pragma unroll
            for (int np = 0; np < 4; np++)
                ldmx4(bfr[np], bw + np * 16 * ROWB + kh * 32);
#pragma unroll
            for (int mf = 0; mf < 4; mf++) {
#pragma unroll
                for (int nf = 0; nf < 8; nf++) {
                    uint32_t bp[2];
                    bp[0] = bfr[nf >> 1][(nf & 1) * 2 + 0];
                    bp[1] = bfr[nf >> 1][(nf & 1) * 2 + 1];
                    mma_bf16(acc[mf][nf], afr[mf], bp);
                }
            }
        }
    }

    // ---- epilogue: add bias, write g_xp (tile may straddle dir boundary) ----
#pragma unroll
    for (int nf = 0; nf < 8; nf++) {
        const int gfrag = n0 + wcol * 64 + nf * 8;        // 8-aligned, never straddles 384
        const int dir = (gfrag >= G3) ? 1 : 0;
        const int g = gfrag - dir * G3 + (lane & 3) * 2;
        const float* bias = dir ? bias_b : bias_f;
        const float bx = bias[g], by = bias[g + 1];
#pragma unroll
        for (int mf = 0; mf < 4; mf++) {
            const int r0 = m0 + wrow * 64 + mf * 16 + (lane >> 2);
            float* d0 = g_xp + ((size_t)dir * MROWS + r0) * G3 + g;
            float* d1 = d0 + (size_t)8 * G3;
            float2 v0 = make_float2(acc[mf][nf][0] + bx, acc[mf][nf][1] + by);
            float2 v1 = make_float2(acc[mf][nf][2] + bx, acc[mf][nf][3] + by);
            *(float2*)d0 = v0;
            *(float2*)d1 = v1;
        }
    }
}

// =================================================================
// Kernel 2: GRU scan — weights in registers, 4 independent f32x2
//   accumulator chains, float2 smem h, prefetched gi.
// =================================================================
__global__ __launch_bounds__(384, 1) void gru_scan(
    const float* __restrict__ w_hh_f, const float* __restrict__ w_hh_b,
    const float* __restrict__ b_hh_f, const float* __restrict__ b_hh_b,
    float* __restrict__ out)
{
    __shared__ float2 h2[64];
    __shared__ float s1[384];
    __shared__ float s2[128];

    const int j   = threadIdx.x;
    const int dir = blockIdx.x & 1;
    const int b   = blockIdx.x >> 1;

    const float* __restrict__ w  = dir ? w_hh_b : w_hh_f;
    const float* __restrict__ bh = dir ? b_hh_b : b_hh_f;

    // weights row j -> 64 packed f32x2 registers
    unsigned long long wp[64];
    const float4* wrow = (const float4*)(w + (size_t)j * HID);
#pragma unroll
    for (int q = 0; q < 32; q++) {
        float4 v = wrow[q];
        float2 p0 = make_float2(v.x, v.y);
        float2 p1 = make_float2(v.z, v.w);
        wp[2 * q]     = *(unsigned long long*)&p0;
        wp[2 * q + 1] = *(unsigned long long*)&p1;
    }
    const float bj = bh[j];
    if (j < 64) h2[j] = make_float2(0.f, 0.f);
    __syncthreads();

    const float* xp_base  = g_xp + ((size_t)dir * MROWS + (size_t)b * T_SZ) * G3;
    float*       out_base = out + (size_t)b * T_SZ * 256 + dir * HID;
    const int t0 = dir ? (T_SZ - 1) : 0;
    const int tstep = dir ? -1 : 1;

    float hprev = 0.f;                       // thread j<128 owns h_j
    float gi = xp_base[(size_t)t0 * G3 + j];

    int t = t0;
    for (int s = 0; s < T_SZ; s++) {
        // prefetch next step's gi (off critical path)
        float gi_next = 0.f;
        if (s + 1 < T_SZ) gi_next = xp_base[(size_t)(t + tstep) * G3 + j];

        // dot(w_row_j, h) with 4 independent chains
        unsigned long long a0 = 0ull, a1 = 0ull, a2 = 0ull, a3 = 0ull;
#pragma unroll
        for (int q = 0; q < 16; q++) {
            float2 h0 = h2[4 * q + 0];
            float2 h1 = h2[4 * q + 1];
            float2 hA = h2[4 * q + 2];
            float2 hB = h2[4 * q + 3];
            a0 = fma2(wp[4 * q + 0], *(unsigned long long*)&h0, a0);
            a1 = fma2(wp[4 * q + 1], *(unsigned long long*)&h1, a1);
            a2 = fma2(wp[4 * q + 2], *(unsigned long long*)&hA, a2);
            a3 = fma2(wp[4 * q + 3], *(unsigned long long*)&hB, a3);
        }
        a0 = add2(a0, a1);
        a2 = add2(a2, a3);
        a0 = add2(a0, a2);
        float2 ap = *(float2*)&a0;
        const float accv = ap.x + ap.y + bj;

        if (j < 256) {
            s1[j] = 1.f / (1.f + __expf(-(accv + gi)));   // r or z, pre-sigmoided
        } else {
            s1[j] = accv;                                  // raw gh_n
            s2[j - 256] = gi;                              // raw gi_n
        }
        __syncthreads();

        if (j < HID) {
            const float r = s1[j];
            const float z = s1[HID + j];
            const float n = tanhf(fmaf(r, s1[2 * HID + j], s2[j]));
            const float hn = (1.f - z) * n + z * hprev;
            hprev = hn;
            ((float*)h2)[j] = hn;
            out_base[(size_t)t * 256 + j] = hn;
        }
        __syncthreads();

        gi = gi_next;
        t += tstep;
    }
}

// =================================================================
// Kernel 3: LayerNorm (ddof=1 std, clamp 1e-6), in place
// =================================================================
__global__ __launch_bounds__(256) void layernorm_rows(
    float* __restrict__ out, const float* __restrict__ ln_w, const float* __restrict__ ln_b)
{
    const size_t row = blockIdx.x;
    const int c = threadIdx.x;
    float* p = out + row * 256;
    const float v = p[c];

    float s = v, ss = v * v;
#pragma unroll
    for (int o = 16; o > 0; o >>= 1) {
        s  += __shfl_xor_sync(0xffffffffu, s, o);
        ss += __shfl_xor_sync(0xffffffffu, ss, o);
    }
    __shared__ float rs[8], rss[8];
    const int wid = c >> 5, lid = c & 31;
    if (lid == 0) { rs[wid] = s; rss[wid] = ss; }
    __syncthreads();
    if (c < 32) {
        s  = (lid < 8) ? rs[lid]  : 0.f;
        ss = (lid < 8) ? rss[lid] : 0.f;
#pragma unroll
        for (int o = 4; o > 0; o >>= 1) {
            s  += __shfl_xor_sync(0xffffffffu, s, o);
            ss += __shfl_xor_sync(0xffffffffu, ss, o);
        }
        if (lid == 0) { rs[0] = s; rss[0] = ss; }
    }
    __syncthreads();
    s = rs[0]; ss = rss[0];

    const float mu  = s * (1.f / 256.f);
    float var = (ss - 256.f * mu * mu) * (1.f / 255.f);
    float sig = sqrtf(fmaxf(var, 0.f));
    sig = fmaxf(sig, 1e-6f);
    p[c] = (v - mu) / sig * ln_w[c] + ln_b[c];
}

// =================================================================
// launch
// =================================================================
extern "C" void kernel_launch(void* const* d_in, const int* in_sizes, int n_in,
                              void* d_out, int out_size)
{
    const float* x      = (const float*)d_in[0];
    const float* w_ih_f = (const float*)d_in[1];
    const float* w_hh_f = (const float*)d_in[2];
    const float* b_ih_f = (const float*)d_in[3];
    const float* b_hh_f = (const float*)d_in[4];
    const float* w_ih_b = (const float*)d_in[5];
    const float* w_hh_b = (const float*)d_in[6];
    const float* b_ih_b = (const float*)d_in[7];
    const float* b_hh_b = (const float*)d_in[8];
    const float* ln_w   = (const float*)d_in[9];
    const float* ln_b   = (const float*)d_in[10];
    float* out = (float*)d_out;

    static bool attrs_set = []() {
        cudaFuncSetAttribute(gemm_mma, cudaFuncAttributeMaxDynamicSharedMemorySize, GEMM_SMEM);
        return true;
    }();
    (void)attrs_set;

    conv_x<<<MROWS, 256>>>(x);
    conv_w<<<NTOT, 256>>>(w_ih_f, w_ih_b);

    dim3 ggrid(NTOT / 256, MROWS / 128);   // (3, 256)
    gemm_mma<<<ggrid, 256, GEMM_SMEM>>>(b_ih_f, b_ih_b);

    gru_scan<<<B_SZ * 2, 384>>>(w_hh_f, w_hh_b, b_hh_f, b_hh_b, out);

    layernorm_rows<<<MROWS, 256>>>(out, ln_w, ln_b);
}

// round 5
// speedup vs baseline: 1.0907x; 1.0907x over previous
#include <cuda_runtime.h>
#include <cuda_bf16.h>
#include <math.h>
#include <stdint.h>

// ---------------- problem constants ----------------
#define B_SZ   64
#define T_SZ   512
#define D_IN   968
#define HID    128
#define G3     384
#define MROWS  (B_SZ * T_SZ)      // 32768
#define KPAD   1024
#define KC2    2048               // [hi | lo] storage
#define NTOT   768

// ---------------- scratch ----------------
__device__ float g_xp[2u * MROWS * G3];
__device__ __nv_bfloat16 g_abf[(size_t)MROWS * KC2];
__device__ __nv_bfloat16 g_wbf[(size_t)NTOT * KC2];

// ---------------- helpers ----------------
__device__ __forceinline__ uint32_t smem_u32(const void* p) {
    uint32_t a;
    asm("{ .reg .u64 t; cvta.to.shared.u64 t, %1; cvt.u32.u64 %0, t; }" : "=r"(a) : "l"(p));
    return a;
}
__device__ __forceinline__ void cp16(uint32_t dst, const void* src) {
    asm volatile("cp.async.cg.shared.global [%0], [%1], 16;" :: "r"(dst), "l"(src));
}
__device__ __forceinline__ void cp_commit() {
    asm volatile("cp.async.commit_group;" ::: "memory");
}
__device__ __forceinline__ void cp_wait2() {
    asm volatile("cp.async.wait_group 2;" ::: "memory");
}
__device__ __forceinline__ void ldmx4(uint32_t* r, uint32_t a) {
    asm volatile("ldmatrix.sync.aligned.m8n8.x4.shared.b16 {%0,%1,%2,%3}, [%4];"
                 : "=r"(r[0]), "=r"(r[1]), "=r"(r[2]), "=r"(r[3]) : "r"(a));
}
__device__ __forceinline__ void mma_bf16(float* c, const uint32_t* a, const uint32_t* b) {
    asm volatile("mma.sync.aligned.m16n8k16.row.col.f32.bf16.bf16.f32 "
                 "{%0,%1,%2,%3}, {%4,%5,%6,%7}, {%8,%9}, {%0,%1,%2,%3};"
                 : "+f"(c[0]), "+f"(c[1]), "+f"(c[2]), "+f"(c[3])
                 : "r"(a[0]), "r"(a[1]), "r"(a[2]), "r"(a[3]), "r"(b[0]), "r"(b[1]));
}
__device__ __forceinline__ unsigned long long fma2(unsigned long long a,
                                                   unsigned long long b,
                                                   unsigned long long c) {
    unsigned long long d;
    asm("fma.rn.f32x2 %0, %1, %2, %3;" : "=l"(d) : "l"(a), "l"(b), "l"(c));
    return d;
}
__device__ __forceinline__ unsigned long long add2(unsigned long long a,
                                                   unsigned long long b) {
    unsigned long long d;
    asm("add.rn.f32x2 %0, %1, %2;" : "=l"(d) : "l"(a), "l"(b));
    return d;
}
__device__ __forceinline__ unsigned long long pack2(float x, float y) {
    float2 t = make_float2(x, y);
    return *(unsigned long long*)&t;
}

// =================================================================
// Kernel 0: fp32 -> split-bf16 [hi | lo], K padded to 1024 each
// =================================================================
__global__ __launch_bounds__(256) void conv_x(const float* __restrict__ x) {
    const int m = blockIdx.x;
    const float* src = x + (size_t)m * D_IN;
    __nv_bfloat16* dst = g_abf + (size_t)m * KC2;
    for (int k = threadIdx.x; k < KPAD; k += 256) {
        float v = (k < D_IN) ? src[k] : 0.f;
        __nv_bfloat16 hi = __float2bfloat16(v);
        __nv_bfloat16 lo = __float2bfloat16(v - __bfloat162float(hi));
        dst[k]        = hi;
        dst[KPAD + k] = lo;
    }
}
__global__ __launch_bounds__(256) void conv_w(const float* __restrict__ w_f,
                                              const float* __restrict__ w_b) {
    const int n = blockIdx.x;
    const float* src = (n < G3) ? (w_f + (size_t)n * D_IN) : (w_b + (size_t)(n - G3) * D_IN);
    __nv_bfloat16* dst = g_wbf + (size_t)n * KC2;
    for (int k = threadIdx.x; k < KPAD; k += 256) {
        float v = (k < D_IN) ? src[k] : 0.f;
        __nv_bfloat16 hi = __float2bfloat16(v);
        __nv_bfloat16 lo = __float2bfloat16(v - __bfloat162float(hi));
        dst[k]        = hi;
        dst[KPAD + k] = lo;
    }
}

// =================================================================
// Kernel 1: HMMA bf16 GEMM, 3-term split via virtual stages.
//   Terms: xhi*whi (s 0..31), xlo*whi (s 32..63), xhi*wlo (s 64..95).
//   CTA 128x128x32, 8 warps (64x32), 3-stage cp.async, 2 CTAs/SM.
// =================================================================
#define BK      32
#define ROWB    80
#define ATILE   (128 * ROWB)
#define STAGEB  (2 * ATILE)
#define NSTG    96
#define GEMM_SMEM (3 * STAGEB)   // 61440

__global__ __launch_bounds__(256, 2) void gemm_mma(const float* __restrict__ bias_f,
                                                   const float* __restrict__ bias_b) {
    extern __shared__ char smem[];
    const uint32_t sb = smem_u32(smem);
    const int tid  = threadIdx.x;
    const int wid  = tid >> 5;
    const int lane = tid & 31;
    const int wrow = wid >> 2;
    const int wcol = wid & 3;

    const int m0 = blockIdx.y * 128;
    const int n0 = blockIdx.x * 128;

    const __nv_bfloat16* Ag = g_abf + (size_t)m0 * KC2;
    const __nv_bfloat16* Bg = g_wbf + (size_t)n0 * KC2;

    const int lrow  = tid >> 1;
    const int lseg0 = (tid & 1) * 2;

    float acc[4][4][4];
#pragma unroll
    for (int i = 0; i < 4; i++)
#pragma unroll
        for (int j = 0; j < 4; j++)
#pragma unroll
            for (int q = 0; q < 4; q++) acc[i][j][q] = 0.f;

    auto issue = [&](int s) {
        int a_k, b_k;
        if (s < 32)      { a_k = s * 32;                b_k = s * 32; }
        else if (s < 64) { a_k = KPAD + (s - 32) * 32;  b_k = (s - 32) * 32; }
        else             { a_k = (s - 64) * 32;         b_k = KPAD + (s - 64) * 32; }
        const uint32_t st = sb + (s % 3) * STAGEB;
        const __nv_bfloat16* arow = Ag + (size_t)lrow * KC2 + a_k;
        const __nv_bfloat16* brow = Bg + (size_t)lrow * KC2 + b_k;
        cp16(st + lrow * ROWB + lseg0 * 16,        arow + lseg0 * 8);
        cp16(st + lrow * ROWB + (lseg0 + 1) * 16,  arow + (lseg0 + 1) * 8);
        cp16(st + ATILE + lrow * ROWB + lseg0 * 16,       brow + lseg0 * 8);
        cp16(st + ATILE + lrow * ROWB + (lseg0 + 1) * 16, brow + (lseg0 + 1) * 8);
    };

    issue(0); cp_commit();
    issue(1); cp_commit();

    const int a_r = (lane & 15);
    const int a_c = (lane >> 4) * 16;
    const int b_r = (lane & 7) + ((lane >> 4) << 3);
    const int b_c = ((lane >> 3) & 1) * 16;

    for (int s = 0; s < NSTG; s++) {
        __syncthreads();
        if (s + 2 < NSTG) issue(s + 2);
        cp_commit();
        cp_wait2();
        __syncthreads();

        const uint32_t st = sb + (s % 3) * STAGEB;
        const uint32_t aw = st + (wrow * 64 + a_r) * ROWB + a_c;
        const uint32_t bw = st + ATILE + (wcol * 32 + b_r) * ROWB + b_c;

#pragma unroll
        for (int kh = 0; kh < 2; kh++) {
            uint32_t afr[4][4], bfr[2][4];
#pragma unroll
            for (int mf = 0; mf < 4; mf++)
                ldmx4(afr[mf], aw + mf * 16 * ROWB + kh * 32);
#pragma unroll
            for (int np = 0; np < 2; np++)
                ldmx4(bfr[np], bw + np * 16 * ROWB + kh * 32);
#pragma unroll
            for (int mf = 0; mf < 4; mf++) {
#pragma unroll
                for (int nf = 0; nf < 4; nf++) {
                    uint32_t bp[2];
                    bp[0] = bfr[nf >> 1][(nf & 1) * 2 + 0];
                    bp[1] = bfr[nf >> 1][(nf & 1) * 2 + 1];
                    mma_bf16(acc[mf][nf], afr[mf], bp);
                }
            }
        }
    }

    const int dir = (n0 >= G3) ? 1 : 0;
    const int gbase = n0 - dir * G3;
    const float* bias = dir ? bias_b : bias_f;

#pragma unroll
    for (int mf = 0; mf < 4; mf++) {
#pragma unroll
        for (int nf = 0; nf < 4; nf++) {
            const int g = gbase + wcol * 32 + nf * 8 + (lane & 3) * 2;
            const float bx = bias[g], by = bias[g + 1];
            const int r0 = m0 + wrow * 64 + mf * 16 + (lane >> 2);
            float* d0 = g_xp + ((size_t)dir * MROWS + r0) * G3 + g;
            float* d1 = d0 + (size_t)8 * G3;
            *(float2*)d0 = make_float2(acc[mf][nf][0] + bx, acc[mf][nf][1] + by);
            *(float2*)d1 = make_float2(acc[mf][nf][2] + bx, acc[mf][nf][3] + by);
        }
    }
}

// =================================================================
// Kernel 2: GRU scan — per-group private h copies, group-redundant
//   gate math, 1 full barrier + 1 named 128-thread barrier per step.
// =================================================================
__global__ __launch_bounds__(384, 1) void gru_scan(
    const float* __restrict__ w_hh_f, const float* __restrict__ w_hh_b,
    const float* __restrict__ b_hh_f, const float* __restrict__ b_hh_b,
    float* __restrict__ out)
{
    __shared__ float4 h2[3][32];          // per-group private h copy
    __shared__ float sA[2][128];          // sigmoid(r)
    __shared__ float sB[2][128];          // sigmoid(z)
    __shared__ float sC[2][128];          // raw gh_n
    __shared__ float sD[2][128];          // raw gi_n

    const int j   = threadIdx.x;
    const int g   = j >> 7;               // gate group 0=r 1=z 2=n
    const int i   = j & 127;              // hidden index
    const int dir = blockIdx.x & 1;
    const int b   = blockIdx.x >> 1;

    const float* __restrict__ w  = dir ? w_hh_b : w_hh_f;
    const float* __restrict__ bh = dir ? b_hh_b : b_hh_f;

    // weights row j -> 64 packed f32x2 registers
    unsigned long long wp[64];
    const float4* wrow = (const float4*)(w + (size_t)j * HID);
#pragma unroll
    for (int q = 0; q < 32; q++) {
        float4 v = wrow[q];
        wp[2 * q]     = pack2(v.x, v.y);
        wp[2 * q + 1] = pack2(v.z, v.w);
    }
    const float bj = bh[j];
    ((float*)&h2[g][0])[i] = 0.f;
    __syncthreads();

    const float* xp_base  = g_xp + ((size_t)dir * MROWS + (size_t)b * T_SZ) * G3;
    float*       out_base = out + (size_t)b * T_SZ * 256 + dir * HID;
    const int t0 = dir ? (T_SZ - 1) : 0;
    const int tstep = dir ? -1 : 1;

    float hprev = 0.f;
    float gi = xp_base[(size_t)t0 * G3 + j];

    int t = t0;
    for (int s = 0; s < T_SZ; s++) {
        const int par = s & 1;

        // ---- phase A: dot(w_j, h) via LDS.128 broadcast, 4 chains ----
        const float4* hv = h2[g];
        unsigned long long a0 = 0ull, a1 = 0ull, a2 = 0ull, a3 = 0ull;
#pragma unroll
        for (int q = 0; q < 8; q++) {
            float4 v0 = hv[4 * q + 0];
            float4 v1 = hv[4 * q + 1];
            float4 v2 = hv[4 * q + 2];
            float4 v3 = hv[4 * q + 3];
            a0 = fma2(wp[8 * q + 0], pack2(v0.x, v0.y), a0);
            a0 = fma2(wp[8 * q + 1], pack2(v0.z, v0.w), a0);
            a1 = fma2(wp[8 * q + 2], pack2(v1.x, v1.y), a1);
            a1 = fma2(wp[8 * q + 3], pack2(v1.z, v1.w), a1);
            a2 = fma2(wp[8 * q + 4], pack2(v2.x, v2.y), a2);
            a2 = fma2(wp[8 * q + 5], pack2(v2.z, v2.w), a2);
            a3 = fma2(wp[8 * q + 6], pack2(v3.x, v3.y), a3);
            a3 = fma2(wp[8 * q + 7], pack2(v3.z, v3.w), a3);
        }
        a0 = add2(a0, a1);
        a2 = add2(a2, a3);
        a0 = add2(a0, a2);
        float2 ap = *(float2*)&a0;
        const float accv = ap.x + ap.y + bj;

        if (g == 0)      sA[par][i] = 1.f / (1.f + __expf(-(accv + gi)));
        else if (g == 1) sB[par][i] = 1.f / (1.f + __expf(-(accv + gi)));
        else             { sC[par][i] = accv; sD[par][i] = gi; }

        // prefetch next gi (overlaps barrier + gate phase)
        float gi_next = 0.f;
        if (s + 1 < T_SZ) gi_next = xp_base[(size_t)(t + tstep) * G3 + j];

        __syncthreads();

        // ---- phase B: redundant h update in every group ----
        const float r = sA[par][i];
        const float z = sB[par][i];
        const float n = tanhf(fmaf(r, sC[par][i], sD[par][i]));
        const float hn = fmaf(z, hprev - n, n);   // (1-z)n + z*h
        hprev = hn;
        ((float*)&h2[g][0])[i] = hn;
        if (g == 0) out_base[(size_t)t * 256 + i] = hn;

        // group-private barrier: h2[g] written by group g only
        asm volatile("bar.sync %0, 128;" :: "r"(g + 1) : "memory");

        gi = gi_next;
        t += tstep;
    }
}

// =================================================================
// Kernel 3: LayerNorm (ddof=1 std, clamp 1e-6), in place
// =================================================================
__global__ __launch_bounds__(256) void layernorm_rows(
    float* __restrict__ out, const float* __restrict__ ln_w, const float* __restrict__ ln_b)
{
    const size_t row = blockIdx.x;
    const int c = threadIdx.x;
    float* p = out + row * 256;
    const float v = p[c];

    float s = v, ss = v * v;
#pragma unroll
    for (int o = 16; o > 0; o >>= 1) {
        s  += __shfl_xor_sync(0xffffffffu, s, o);
        ss += __shfl_xor_sync(0xffffffffu, ss, o);
    }
    __shared__ float rs[8], rss[8];
    const int wid = c >> 5, lid = c & 31;
    if (lid == 0) { rs[wid] = s; rss[wid] = ss; }
    __syncthreads();
    if (c < 32) {
        s  = (lid < 8) ? rs[lid]  : 0.f;
        ss = (lid < 8) ? rss[lid] : 0.f;
#pragma unroll
        for (int o = 4; o > 0; o >>= 1) {
            s  += __shfl_xor_sync(0xffffffffu, s, o);
            ss += __shfl_xor_sync(0xffffffffu, ss, o);
        }
        if (lid == 0) { rs[0] = s; rss[0] = ss; }
    }
    __syncthreads();
    s = rs[0]; ss = rss[0];

    const float mu  = s * (1.f / 256.f);
    float var = (ss - 256.f * mu * mu) * (1.f / 255.f);
    float sig = sqrtf(fmaxf(var, 0.f));
    sig = fmaxf(sig, 1e-6f);
    p[c] = (v - mu) / sig * ln_w[c] + ln_b[c];
}

// =================================================================
// launch
// =================================================================
extern "C" void kernel_launch(void* const* d_in, const int* in_sizes, int n_in,
                              void* d_out, int out_size)
{
    const float* x      = (const float*)d_in[0];
    const float* w_ih_f = (const float*)d_in[1];
    const float* w_hh_f = (const float*)d_in[2];
    const float* b_ih_f = (const float*)d_in[3];
    const float* b_hh_f = (const float*)d_in[4];
    const float* w_ih_b = (const float*)d_in[5];
    const float* w_hh_b = (const float*)d_in[6];
    const float* b_ih_b = (const float*)d_in[7];
    const float* b_hh_b = (const float*)d_in[8];
    const float* ln_w   = (const float*)d_in[9];
    const float* ln_b   = (const float*)d_in[10];
    float* out = (float*)d_out;

    static bool attrs_set = []() {
        cudaFuncSetAttribute(gemm_mma, cudaFuncAttributeMaxDynamicSharedMemorySize, GEMM_SMEM);
        return true;
    }();
    (void)attrs_set;

    conv_x<<<MROWS, 256>>>(x);
    conv_w<<<NTOT, 256>>>(w_ih_f, w_ih_b);

    dim3 ggrid(NTOT / 128, MROWS / 128);   // (6, 256) — N fastest for A L2 reuse
    gemm_mma<<<ggrid, 256, GEMM_SMEM>>>(b_ih_f, b_ih_b);

    gru_scan<<<B_SZ * 2, 384>>>(w_hh_f, w_hh_b, b_hh_f, b_hh_b, out);

    layernorm_rows<<<MROWS, 256>>>(out, ln_w, ln_b);
}

// round 6
// speedup vs baseline: 1.4267x; 1.3081x over previous
#include <cuda_runtime.h>
#include <cuda_fp16.h>
#include <math.h>
#include <stdint.h>

// ---------------- problem constants ----------------
#define B_SZ   64
#define T_SZ   512
#define D_IN   968
#define HID    128
#define G3     384
#define MROWS  (B_SZ * T_SZ)      // 32768
#define KPAD   1024
#define KC2    2048               // A storage: [hi | lo]
#define KW     1024               // W storage: hi only
#define NTOT   768

// ---------------- scratch ----------------
__device__ float g_xp[2u * MROWS * G3];
__device__ __half g_abf[(size_t)MROWS * KC2];
__device__ __half g_wbf[(size_t)NTOT * KW];

// ---------------- helpers ----------------
__device__ __forceinline__ uint32_t smem_u32(const void* p) {
    uint32_t a;
    asm("{ .reg .u64 t; cvta.to.shared.u64 t, %1; cvt.u32.u64 %0, t; }" : "=r"(a) : "l"(p));
    return a;
}
__device__ __forceinline__ void cp16(uint32_t dst, const void* src) {
    asm volatile("cp.async.cg.shared.global [%0], [%1], 16;" :: "r"(dst), "l"(src));
}
__device__ __forceinline__ void cp_commit() {
    asm volatile("cp.async.commit_group;" ::: "memory");
}
__device__ __forceinline__ void cp_wait2() {
    asm volatile("cp.async.wait_group 2;" ::: "memory");
}
__device__ __forceinline__ void ldmx4(uint32_t* r, uint32_t a) {
    asm volatile("ldmatrix.sync.aligned.m8n8.x4.shared.b16 {%0,%1,%2,%3}, [%4];"
                 : "=r"(r[0]), "=r"(r[1]), "=r"(r[2]), "=r"(r[3]) : "r"(a));
}
__device__ __forceinline__ void mma_f16(float* c, const uint32_t* a, const uint32_t* b) {
    asm volatile("mma.sync.aligned.m16n8k16.row.col.f32.f16.f16.f32 "
                 "{%0,%1,%2,%3}, {%4,%5,%6,%7}, {%8,%9}, {%0,%1,%2,%3};"
                 : "+f"(c[0]), "+f"(c[1]), "+f"(c[2]), "+f"(c[3])
                 : "r"(a[0]), "r"(a[1]), "r"(a[2]), "r"(a[3]), "r"(b[0]), "r"(b[1]));
}
__device__ __forceinline__ unsigned long long fma2(unsigned long long a,
                                                   unsigned long long b,
                                                   unsigned long long c) {
    unsigned long long d;
    asm("fma.rn.f32x2 %0, %1, %2, %3;" : "=l"(d) : "l"(a), "l"(b), "l"(c));
    return d;
}
__device__ __forceinline__ unsigned long long add2(unsigned long long a,
                                                   unsigned long long b) {
    unsigned long long d;
    asm("add.rn.f32x2 %0, %1, %2;" : "=l"(d) : "l"(a), "l"(b));
    return d;
}
__device__ __forceinline__ unsigned long long pack2(float x, float y) {
    float2 t = make_float2(x, y);
    return *(unsigned long long*)&t;
}
__device__ __forceinline__ float fast_sigmoid(float x) {
    return __fdividef(1.f, 1.f + __expf(-x));
}
__device__ __forceinline__ float fast_tanh(float y) {
    const float e = __expf(-2.f * fabsf(y));           // in (0,1]
    const float n = __fdividef(1.f - e, 1.f + e);      // |tanh|
    return copysignf(n, y);
}

// =================================================================
// Kernel 0: fp32 -> fp16 split
// =================================================================
__global__ __launch_bounds__(256) void conv_x(const float* __restrict__ x) {
    const int m = blockIdx.x;
    const float* src = x + (size_t)m * D_IN;
    __half* dst = g_abf + (size_t)m * KC2;
    for (int k = threadIdx.x; k < KPAD; k += 256) {
        float v = (k < D_IN) ? src[k] : 0.f;
        __half hi = __float2half(v);
        __half lo = __float2half(v - __half2float(hi));
        dst[k]        = hi;
        dst[KPAD + k] = lo;
    }
}
__global__ __launch_bounds__(256) void conv_w(const float* __restrict__ w_f,
                                              const float* __restrict__ w_b) {
    const int n = blockIdx.x;
    const float* src = (n < G3) ? (w_f + (size_t)n * D_IN) : (w_b + (size_t)(n - G3) * D_IN);
    __half* dst = g_wbf + (size_t)n * KW;
    for (int k = threadIdx.x; k < KPAD; k += 256) {
        float v = (k < D_IN) ? src[k] : 0.f;
        dst[k] = __float2half(v);
    }
}

// =================================================================
// Kernel 1: HMMA fp16 GEMM, 2-term split via virtual stages.
//   Terms: xhi*w (s 0..31), xlo*w (s 32..63).
//   CTA 128x128x32, 8 warps (64x32), 3-stage cp.async, 2 CTAs/SM.
// =================================================================
#define BK      32
#define ROWB    80
#define ATILE   (128 * ROWB)
#define STAGEB  (2 * ATILE)
#define NSTG    64
#define GEMM_SMEM (3 * STAGEB)   // 61440

__global__ __launch_bounds__(256, 2) void gemm_mma(const float* __restrict__ bias_f,
                                                   const float* __restrict__ bias_b) {
    extern __shared__ char smem[];
    const uint32_t sb = smem_u32(smem);
    const int tid  = threadIdx.x;
    const int wid  = tid >> 5;
    const int lane = tid & 31;
    const int wrow = wid >> 2;
    const int wcol = wid & 3;

    const int m0 = blockIdx.y * 128;
    const int n0 = blockIdx.x * 128;

    const __half* Ag = g_abf + (size_t)m0 * KC2;
    const __half* Bg = g_wbf + (size_t)n0 * KW;

    const int lrow  = tid >> 1;
    const int lseg0 = (tid & 1) * 2;

    float acc[4][4][4];
#pragma unroll
    for (int i = 0; i < 4; i++)
#pragma unroll
        for (int j = 0; j < 4; j++)
#pragma unroll
            for (int q = 0; q < 4; q++) acc[i][j][q] = 0.f;

    auto issue = [&](int s) {
        const int a_k = (s < 32) ? s * 32 : KPAD + (s - 32) * 32;
        const int b_k = (s < 32) ? s * 32 : (s - 32) * 32;
        const uint32_t st = sb + (s % 3) * STAGEB;
        const __half* arow = Ag + (size_t)lrow * KC2 + a_k;
        const __half* brow = Bg + (size_t)lrow * KW + b_k;
        cp16(st + lrow * ROWB + lseg0 * 16,        arow + lseg0 * 8);
        cp16(st + lrow * ROWB + (lseg0 + 1) * 16,  arow + (lseg0 + 1) * 8);
        cp16(st + ATILE + lrow * ROWB + lseg0 * 16,       brow + lseg0 * 8);
        cp16(st + ATILE + lrow * ROWB + (lseg0 + 1) * 16, brow + (lseg0 + 1) * 8);
    };

    issue(0); cp_commit();
    issue(1); cp_commit();

    const int a_r = (lane & 15);
    const int a_c = (lane >> 4) * 16;
    const int b_r = (lane & 7) + ((lane >> 4) << 3);
    const int b_c = ((lane >> 3) & 1) * 16;

    for (int s = 0; s < NSTG; s++) {
        __syncthreads();
        if (s + 2 < NSTG) issue(s + 2);
        cp_commit();
        cp_wait2();
        __syncthreads();

        const uint32_t st = sb + (s % 3) * STAGEB;
        const uint32_t aw = st + (wrow * 64 + a_r) * ROWB + a_c;
        const uint32_t bw = st + ATILE + (wcol * 32 + b_r) * ROWB + b_c;

#pragma unroll
        for (int kh = 0; kh < 2; kh++) {
            uint32_t afr[4][4], bfr[2][4];
#pragma unroll
            for (int mf = 0; mf < 4; mf++)
                ldmx4(afr[mf], aw + mf * 16 * ROWB + kh * 32);
#pragma unroll
            for (int np = 0; np < 2; np++)
                ldmx4(bfr[np], bw + np * 16 * ROWB + kh * 32);
#pragma unroll
            for (int mf = 0; mf < 4; mf++) {
#pragma unroll
                for (int nf = 0; nf < 4; nf++) {
                    uint32_t bp[2];
                    bp[0] = bfr[nf >> 1][(nf & 1) * 2 + 0];
                    bp[1] = bfr[nf >> 1][(nf & 1) * 2 + 1];
                    mma_f16(acc[mf][nf], afr[mf], bp);
                }
            }
        }
    }

    const int dir = (n0 >= G3) ? 1 : 0;
    const int gbase = n0 - dir * G3;
    const float* bias = dir ? bias_b : bias_f;

#pragma unroll
    for (int mf = 0; mf < 4; mf++) {
#pragma unroll
        for (int nf = 0; nf < 4; nf++) {
            const int g = gbase + wcol * 32 + nf * 8 + (lane & 3) * 2;
            const float bx = bias[g], by = bias[g + 1];
            const int r0 = m0 + wrow * 64 + mf * 16 + (lane >> 2);
            float* d0 = g_xp + ((size_t)dir * MROWS + r0) * G3 + g;
            float* d1 = d0 + (size_t)8 * G3;
            *(float2*)d0 = make_float2(acc[mf][nf][0] + bx, acc[mf][nf][1] + by);
            *(float2*)d1 = make_float2(acc[mf][nf][2] + bx, acc[mf][nf][3] + by);
        }
    }
}

// =================================================================
// Kernel 2: GRU scan — R4 structure + approx activations,
//   phase B on n-gate group (registers), 2-step gi prefetch.
// =================================================================
__global__ __launch_bounds__(384, 1) void gru_scan(
    const float* __restrict__ w_hh_f, const float* __restrict__ w_hh_b,
    const float* __restrict__ b_hh_f, const float* __restrict__ b_hh_b,
    float* __restrict__ out)
{
    __shared__ float4 h4s[32];            // h vector (float4 view)
    __shared__ float sR[128];             // sigmoid(r)
    __shared__ float sZ[128];             // sigmoid(z)

    const int j   = threadIdx.x;
    const int g   = j >> 7;               // 0=r 1=z 2=n
    const int i   = j & 127;
    const int dir = blockIdx.x & 1;
    const int b   = blockIdx.x >> 1;

    const float* __restrict__ w  = dir ? w_hh_b : w_hh_f;
    const float* __restrict__ bh = dir ? b_hh_b : b_hh_f;

    unsigned long long wp[64];
    const float4* wrow = (const float4*)(w + (size_t)j * HID);
#pragma unroll
    for (int q = 0; q < 32; q++) {
        float4 v = wrow[q];
        wp[2 * q]     = pack2(v.x, v.y);
        wp[2 * q + 1] = pack2(v.z, v.w);
    }
    const float bj = bh[j];
    if (j < 32) h4s[j] = make_float4(0.f, 0.f, 0.f, 0.f);
    __syncthreads();

    const float* xp_base  = g_xp + ((size_t)dir * MROWS + (size_t)b * T_SZ) * G3;
    float*       out_base = out + (size_t)b * T_SZ * 256 + dir * HID;
    const int t0 = dir ? (T_SZ - 1) : 0;
    const int tstep = dir ? -1 : 1;

    float hprev = 0.f;
    float gi0 = xp_base[(size_t)t0 * G3 + j];
    float gi1 = (T_SZ > 1) ? xp_base[(size_t)(t0 + tstep) * G3 + j] : 0.f;

    int t = t0;
    for (int s = 0; s < T_SZ; s++) {
        // prefetch step s+2 early (covers DRAM latency across whole step)
        float gi2 = 0.f;
        if (s + 2 < T_SZ) gi2 = xp_base[(size_t)(t + 2 * tstep) * G3 + j];

        // ---- phase A: dot(w_j, h) via LDS.128 broadcast, 4 chains ----
        unsigned long long a0 = 0ull, a1 = 0ull, a2 = 0ull, a3 = 0ull;
#pragma unroll
        for (int q = 0; q < 8; q++) {
            float4 v0 = h4s[4 * q + 0];
            float4 v1 = h4s[4 * q + 1];
            float4 v2 = h4s[4 * q + 2];
            float4 v3 = h4s[4 * q + 3];
            a0 = fma2(wp[8 * q + 0], pack2(v0.x, v0.y), a0);
            a0 = fma2(wp[8 * q + 1], pack2(v0.z, v0.w), a0);
            a1 = fma2(wp[8 * q + 2], pack2(v1.x, v1.y), a1);
            a1 = fma2(wp[8 * q + 3], pack2(v1.z, v1.w), a1);
            a2 = fma2(wp[8 * q + 4], pack2(v2.x, v2.y), a2);
            a2 = fma2(wp[8 * q + 5], pack2(v2.z, v2.w), a2);
            a3 = fma2(wp[8 * q + 6], pack2(v3.x, v3.y), a3);
            a3 = fma2(wp[8 * q + 7], pack2(v3.z, v3.w), a3);
        }
        a0 = add2(a0, a1);
        a2 = add2(a2, a3);
        a0 = add2(a0, a2);
        float2 ap = *(float2*)&a0;
        const float accv = ap.x + ap.y + bj;   // gh_g (+b_hh)

        if (g == 0)      sR[i] = fast_sigmoid(accv + gi0);
        else if (g == 1) sZ[i] = fast_sigmoid(accv + gi0);
        // g==2 keeps gh_n=accv, gi_n=gi0 in registers

        __syncthreads();

        // ---- phase B: n-gate group updates h (has gh_n/gi_n in regs) ----
        if (g == 2) {
            const float r = sR[i];
            const float z = sZ[i];
            const float n = fast_tanh(fmaf(r, accv, gi0));
            const float hn = fmaf(z, hprev - n, n);
            hprev = hn;
            ((float*)h4s)[i] = hn;
            out_base[(size_t)t * 256 + i] = hn;
        }
        __syncthreads();

        gi0 = gi1;
        gi1 = gi2;
        t += tstep;
    }
}

// =================================================================
// Kernel 3: LayerNorm (ddof=1 std, clamp 1e-6), in place
// =================================================================
__global__ __launch_bounds__(256) void layernorm_rows(
    float* __restrict__ out, const float* __restrict__ ln_w, const float* __restrict__ ln_b)
{
    const size_t row = blockIdx.x;
    const int c = threadIdx.x;
    float* p = out + row * 256;
    const float v = p[c];

    float s = v, ss = v * v;
#pragma unroll
    for (int o = 16; o > 0; o >>= 1) {
        s  += __shfl_xor_sync(0xffffffffu, s, o);
        ss += __shfl_xor_sync(0xffffffffu, ss, o);
    }
    __shared__ float rs[8], rss[8];
    const int wid = c >> 5, lid = c & 31;
    if (lid == 0) { rs[wid] = s; rss[wid] = ss; }
    __syncthreads();
    if (c < 32) {
        s  = (lid < 8) ? rs[lid]  : 0.f;
        ss = (lid < 8) ? rss[lid] : 0.f;
#pragma unroll
        for (int o = 4; o > 0; o >>= 1) {
            s  += __shfl_xor_sync(0xffffffffu, s, o);
            ss += __shfl_xor_sync(0xffffffffu, ss, o);
        }
        if (lid == 0) { rs[0] = s; rss[0] = ss; }
    }
    __syncthreads();
    s = rs[0]; ss = rss[0];

    const float mu  = s * (1.f / 256.f);
    float var = (ss - 256.f * mu * mu) * (1.f / 255.f);
    float sig = sqrtf(fmaxf(var, 0.f));
    sig = fmaxf(sig, 1e-6f);
    p[c] = (v - mu) / sig * ln_w[c] + ln_b[c];
}

// =================================================================
// launch
// =================================================================
extern "C" void kernel_launch(void* const* d_in, const int* in_sizes, int n_in,
                              void* d_out, int out_size)
{
    const float* x      = (const float*)d_in[0];
    const float* w_ih_f = (const float*)d_in[1];
    const float* w_hh_f = (const float*)d_in[2];
    const float* b_ih_f = (const float*)d_in[3];
    const float* b_hh_f = (const float*)d_in[4];
    const float* w_ih_b = (const float*)d_in[5];
    const float* w_hh_b = (const float*)d_in[6];
    const float* b_ih_b = (const float*)d_in[7];
    const float* b_hh_b = (const float*)d_in[8];
    const float* ln_w   = (const float*)d_in[9];
    const float* ln_b   = (const float*)d_in[10];
    float* out = (float*)d_out;

    static bool attrs_set = []() {
        cudaFuncSetAttribute(gemm_mma, cudaFuncAttributeMaxDynamicSharedMemorySize, GEMM_SMEM);
        return true;
    }();
    (void)attrs_set;

    conv_x<<<MROWS, 256>>>(x);
    conv_w<<<NTOT, 256>>>(w_ih_f, w_ih_b);

    dim3 ggrid(NTOT / 128, MROWS / 128);   // (6, 256)
    gemm_mma<<<ggrid, 256, GEMM_SMEM>>>(b_ih_f, b_ih_b);

    gru_scan<<<B_SZ * 2, 384>>>(w_hh_f, w_hh_b, b_hh_f, b_hh_b, out);

    layernorm_rows<<<MROWS, 256>>>(out, ln_w, ln_b);
}